// round 15
// baseline (speedup 1.0000x reference)
#include <cuda_runtime.h>
#include <cuda_fp16.h>
#include <cuda_bf16.h>
#include <cstdint>

#define N_NODES 50000
#define N_EDGES 1600000
#define DIM 128

// ---------------- scratch (allocation-free) ----------------
__device__ int           g_row_off[N_NODES + 1];
__device__ __half        g_Hh[(size_t)N_NODES * DIM];   // fp16 copy of H, 12.8 MB
__device__ float         g_agg[(size_t)N_NODES * DIM];  // aggregated features, 25.6 MB
__device__ unsigned short g_Wth[DIM * DIM];             // bf16 hi of W^T, [n][k], 32 KB
__device__ unsigned short g_Wtl[DIM * DIM];             // bf16 lo of W^T, [n][k], 32 KB

// packed f32x2 FMA: d += a*b
#define FFMA2(d, a, b) asm("fma.rn.f32x2 %0, %1, %2, %0;" : "+l"(d) : "l"(a), "l"(b))

__device__ __forceinline__ unsigned long long dup2(float v) {
    unsigned long long d;
    unsigned u = __float_as_uint(v);
    asm("mov.b64 %0, {%1, %1};" : "=l"(d) : "r"(u));
    return d;
}
__device__ __forceinline__ unsigned long long pack2(float2 v) {
    unsigned long long d;
    asm("mov.b64 %0, {%1, %2};" : "=l"(d) : "r"(__float_as_uint(v.x)), "r"(__float_as_uint(v.y)));
    return d;
}
__device__ __forceinline__ float lo32(unsigned long long v) { return __uint_as_float((unsigned)v); }
__device__ __forceinline__ float hi32(unsigned long long v) { return __uint_as_float((unsigned)(v >> 32)); }

__device__ __forceinline__ uint32_t smem_u32(const void* p) {
    uint32_t a;
    asm("{ .reg .u64 t; cvta.to.shared.u64 t, %1; cvt.u32.u64 %0, t; }" : "=r"(a) : "l"(p));
    return a;
}

// bf16 hi/lo split of a float pair -> two packed bf16x2
__device__ __forceinline__ void bf16_split2(float x, float y, uint32_t& hi, uint32_t& lo) {
    const __nv_bfloat162 h = __floats2bfloat162_rn(x, y);
    hi = *(const uint32_t*)&h;
    const float rx = x - __bfloat162float(__low2bfloat16(h));
    const float ry = y - __bfloat162float(__high2bfloat16(h));
    const __nv_bfloat162 l = __floats2bfloat162_rn(rx, ry);
    lo = *(const uint32_t*)&l;
}

// mma.sync m16n8k16 row.col f32 += bf16 * bf16
#define MMA_BF16(d, a, b)                                                        \
    asm volatile("mma.sync.aligned.m16n8k16.row.col.f32.bf16.bf16.f32 "          \
        "{%0,%1,%2,%3}, {%4,%5,%6,%7}, {%8,%9}, {%0,%1,%2,%3};"                  \
        : "+f"((d)[0]), "+f"((d)[1]), "+f"((d)[2]), "+f"((d)[3])                 \
        : "r"((a)[0]), "r"((a)[1]), "r"((a)[2]), "r"((a)[3]),                    \
          "r"((b)[0]), "r"((b)[1]))

#define LDMATRIX_X4(r, addr)                                                     \
    asm volatile("ldmatrix.sync.aligned.m8n8.x4.shared.b16 {%0,%1,%2,%3}, [%4];" \
        : "=r"((r)[0]), "=r"((r)[1]), "=r"((r)[2]), "=r"((r)[3]) : "r"(addr))

// ---------------- Kernel A0: convert H -> fp16 ----------------
__global__ void convert_kernel(const float* __restrict__ H) {
    const int i = blockIdx.x * blockDim.x + threadIdx.x;
    if (i >= N_NODES * DIM / 4) return;
    const float4 v = ((const float4*)H)[i];
    const __half2 h0 = __floats2half2_rn(v.x, v.y);
    const __half2 h1 = __floats2half2_rn(v.z, v.w);
    uint2 o;
    o.x = *(const unsigned*)&h0;
    o.y = *(const unsigned*)&h1;
    ((uint2*)g_Hh)[i] = o;
}

// ---------------- Kernel A1: W^T -> bf16 hi/lo  (Wt[n][k] = W[k][n]) ----------------
__global__ void prep_w_kernel(const float* __restrict__ W) {
    const int i = blockIdx.x * blockDim.x + threadIdx.x;
    if (i >= DIM * DIM) return;
    const int n = i >> 7, k = i & 127;
    const float w = W[k * DIM + n];
    const __nv_bfloat16 bh = __float2bfloat16(w);
    const float rem = w - __bfloat162float(bh);
    const __nv_bfloat16 bl = __float2bfloat16(rem);
    g_Wth[n * DIM + k] = *(const unsigned short*)&bh;
    g_Wtl[n * DIM + k] = *(const unsigned short*)&bl;
}

// ---------------- Kernel A2: offsets via coalesced boundary scan ----------------
__global__ void scan_offsets_kernel(const int* __restrict__ dst) {
    __shared__ int sd[257];
    const int i = blockIdx.x * blockDim.x + threadIdx.x;
    const int t = threadIdx.x;
    int d = (i < N_EDGES) ? dst[i] : N_NODES;
    sd[t + 1] = d;
    if (t == 0) sd[0] = (i == 0) ? -1 : dst[i - 1];
    __syncthreads();
    if (i >= N_EDGES) return;
    const int prev = sd[t];
    for (int j = prev + 1; j <= d; j++) g_row_off[j] = i;
    if (i == N_EDGES - 1) {
        for (int j = d + 1; j <= N_NODES; j++) g_row_off[j] = N_EDGES;
    }
}

// ---------------- Kernel B: gather-aggregate, warp-per-node, fp16 H ----------------
__global__ __launch_bounds__(256)
void gather_kernel(const int* __restrict__ esrc,
                   const float* __restrict__ ew)
{
    const int lane = threadIdx.x & 31;
    const int node = blockIdx.x * 8 + (threadIdx.x >> 5);

    const int s = g_row_off[node];
    const int e = g_row_off[node + 1];

    const uint2* __restrict__ Hh2 = (const uint2*)g_Hh;
    unsigned long long acc0 = 0ull, acc1 = 0ull;

    #pragma unroll 1
    for (int p = s; p < e; p += 32) {
        const int idx = p + lane;
        int   src = 0;
        float w   = 0.f;
        if (idx < e) { src = esrc[idx]; w = ew[idx]; }
        const int cnt = min(32, e - p);
        if (cnt == 32) {
            #pragma unroll
            for (int g = 0; g < 32; g += 4) {
                int   ss[4];
                float ws[4];
                #pragma unroll
                for (int i = 0; i < 4; i++) {
                    ss[i] = __shfl_sync(0xffffffffu, src, g + i);
                    ws[i] = __shfl_sync(0xffffffffu, w,   g + i);
                }
                uint2 hv[4];
                #pragma unroll
                for (int i = 0; i < 4; i++)
                    hv[i] = Hh2[(size_t)ss[i] * 32 + lane];
                #pragma unroll
                for (int i = 0; i < 4; i++) {
                    const unsigned long long wd = dup2(ws[i]);
                    const float2 f01 = __half22float2(*(const __half2*)&hv[i].x);
                    const float2 f23 = __half22float2(*(const __half2*)&hv[i].y);
                    FFMA2(acc0, wd, pack2(f01));
                    FFMA2(acc1, wd, pack2(f23));
                }
            }
        } else {
            #pragma unroll 1
            for (int g = 0; g < cnt; g += 4) {
                int   ss[4];
                float ws[4];
                #pragma unroll
                for (int i = 0; i < 4; i++) {
                    ss[i] = __shfl_sync(0xffffffffu, src, g + i);
                    ws[i] = __shfl_sync(0xffffffffu, w,   g + i);
                }
                uint2 hv[4];
                #pragma unroll
                for (int i = 0; i < 4; i++)
                    hv[i] = Hh2[(size_t)ss[i] * 32 + lane];
                #pragma unroll
                for (int i = 0; i < 4; i++) {
                    const unsigned long long wd = dup2(ws[i]);
                    const float2 f01 = __half22float2(*(const __half2*)&hv[i].x);
                    const float2 f23 = __half22float2(*(const __half2*)&hv[i].y);
                    FFMA2(acc0, wd, pack2(f01));
                    FFMA2(acc1, wd, pack2(f23));
                }
            }
        }
    }

    float4 st;
    st.x = lo32(acc0); st.y = hi32(acc0);
    st.z = lo32(acc1); st.w = hi32(acc1);
    ((float4*)g_agg)[(size_t)node * 32 + lane] = st;
}

// ---------------- Kernel C: mma.sync bf16-split GEMM: out = agg @ W + b ----------------
// Block: 64 rows x 128 cols, 8 warps; warp w owns 16-col strip [w*16, w*16+16).
// A tile staged once to smem as bf16 hi/lo (272 B padded row stride, ldmatrix-friendly).
// D = Ah*Bh + Ah*Bl + Al*Bh, fp32 accum.
#define A_STRIDE 272
__global__ __launch_bounds__(256)
void tensor_gemm_kernel(const float* __restrict__ bias, float* __restrict__ out)
{
    __shared__ __align__(16) unsigned char sAh[64 * A_STRIDE];   // 17 KB
    __shared__ __align__(16) unsigned char sAl[64 * A_STRIDE];   // 17 KB

    const int tid  = threadIdx.x;
    const int wid  = tid >> 5;
    const int lane = tid & 31;
    const int base = blockIdx.x * 64;

    // ---- stage A tile: f32 -> bf16 hi/lo in smem ----
    const float4* __restrict__ A4 = (const float4*)g_agg;
    #pragma unroll
    for (int j = tid; j < 64 * 32; j += 256) {      // 2048 float4 slots
        const int row = j >> 5;
        const int c4  = j & 31;
        int gr = base + row;
        if (gr >= N_NODES) gr = N_NODES - 1;
        const float4 v = A4[(size_t)gr * 32 + c4];
        uint32_t h01, l01, h23, l23;
        bf16_split2(v.x, v.y, h01, l01);
        bf16_split2(v.z, v.w, h23, l23);
        const uint32_t off = row * A_STRIDE + c4 * 8;
        *(uint32_t*)(sAh + off)     = h01;
        *(uint32_t*)(sAh + off + 4) = h23;
        *(uint32_t*)(sAl + off)     = l01;
        *(uint32_t*)(sAl + off + 4) = l23;
    }
    __syncthreads();

    // ---- per-warp B fragments (hi & lo), held in registers, loaded from L1-hot Wt ----
    const int g  = lane >> 2;     // groupID: output row offset / B col
    const int tg = lane & 3;      // thread in group
    uint32_t bh[2][8][2], bl[2][8][2];
    {
        const uint32_t* __restrict__ Wh32 = (const uint32_t*)g_Wth;   // [n][k] as 64 u32/row
        const uint32_t* __restrict__ Wl32 = (const uint32_t*)g_Wtl;
        #pragma unroll
        for (int nt = 0; nt < 2; nt++) {
            const int n = wid * 16 + nt * 8 + g;
            #pragma unroll
            for (int ks = 0; ks < 8; ks++) {
                bh[nt][ks][0] = Wh32[n * 64 + ks * 8 + tg];
                bh[nt][ks][1] = Wh32[n * 64 + ks * 8 + tg + 4];
                bl[nt][ks][0] = Wl32[n * 64 + ks * 8 + tg];
                bl[nt][ks][1] = Wl32[n * 64 + ks * 8 + tg + 4];
            }
        }
    }

    // ldmatrix lane address pattern: lanes 0-7 rows 0-7 k0, 8-15 rows 8-15 k0,
    // 16-23 rows 0-7 k8, 24-31 rows 8-15 k8
    const int lrow  = (lane & 7) + ((lane & 8) ? 8 : 0);
    const int lcolb = (lane & 16) ? 16 : 0;
    const uint32_t sAh_u = smem_u32(sAh);
    const uint32_t sAl_u = smem_u32(sAl);

    // bias for this thread's 2x2 output cols
    float2 bv[2];
    #pragma unroll
    for (int nt = 0; nt < 2; nt++)
        bv[nt] = *(const float2*)&bias[wid * 16 + nt * 8 + tg * 2];

    #pragma unroll 1
    for (int rt = 0; rt < 4; rt++) {
        float acc[2][4];
        #pragma unroll
        for (int nt = 0; nt < 2; nt++)
            #pragma unroll
            for (int i = 0; i < 4; i++) acc[nt][i] = 0.f;

        #pragma unroll
        for (int ks = 0; ks < 8; ks++) {
            const uint32_t off = (rt * 16 + lrow) * A_STRIDE + ks * 32 + lcolb;
            uint32_t ah[4], al[4];
            LDMATRIX_X4(ah, sAh_u + off);
            LDMATRIX_X4(al, sAl_u + off);
            #pragma unroll
            for (int nt = 0; nt < 2; nt++) {
                MMA_BF16(acc[nt], ah, bh[nt][ks]);
                MMA_BF16(acc[nt], ah, bl[nt][ks]);
                MMA_BF16(acc[nt], al, bh[nt][ks]);
            }
        }

        // store: thread owns rows (rt*16+g, rt*16+g+8), cols (2tg, 2tg+1) per ntile
        const int r0 = base + rt * 16 + g;
        const int r1 = r0 + 8;
        #pragma unroll
        for (int nt = 0; nt < 2; nt++) {
            const int col = wid * 16 + nt * 8 + tg * 2;
            if (r0 < N_NODES) {
                float2 o;
                o.x = acc[nt][0] + bv[nt].x;
                o.y = acc[nt][1] + bv[nt].y;
                *(float2*)&out[(size_t)r0 * DIM + col] = o;
            }
            if (r1 < N_NODES) {
                float2 o;
                o.x = acc[nt][2] + bv[nt].x;
                o.y = acc[nt][3] + bv[nt].y;
                *(float2*)&out[(size_t)r1 * DIM + col] = o;
            }
        }
    }
}

extern "C" void kernel_launch(void* const* d_in, const int* in_sizes, int n_in,
                              void* d_out, int out_size) {
    const float* H    = (const float*)d_in[0];
    const int*   esrc = (const int*)  d_in[1];
    const int*   edst = (const int*)  d_in[2];
    const float* ew   = (const float*)d_in[3];
    const float* W    = (const float*)d_in[4];
    const float* b    = (const float*)d_in[5];
    float* out = (float*)d_out;

    convert_kernel<<<(N_NODES * DIM / 4 + 255) / 256, 256>>>(H);
    prep_w_kernel<<<(DIM * DIM + 255) / 256, 256>>>(W);
    scan_offsets_kernel<<<(N_EDGES + 255) / 256, 256>>>(edst);
    gather_kernel<<<N_NODES / 8, 256>>>(esrc, ew);
    tensor_gemm_kernel<<<(N_NODES + 63) / 64, 256>>>(b, out);
}

// round 17
// speedup vs baseline: 1.6738x; 1.6738x over previous
#include <cuda_runtime.h>
#include <cuda_fp16.h>
#include <cuda_bf16.h>
#include <cstdint>

#define N_NODES 50000
#define N_EDGES 1600000
#define DIM 128

// ---------------- scratch (allocation-free) ----------------
__device__ int            g_row_off[N_NODES + 1];
__device__ __half         g_Hh[(size_t)N_NODES * DIM];   // fp16 copy of H, 12.8 MB
__device__ float          g_agg[(size_t)N_NODES * DIM];  // aggregated features, 25.6 MB
__device__ unsigned short g_Wth[DIM * DIM];              // bf16 hi of W^T, [n][k], 32 KB
__device__ unsigned short g_Wtl[DIM * DIM];              // bf16 lo of W^T, [n][k], 32 KB

// packed f32x2 FMA: d += a*b
#define FFMA2(d, a, b) asm("fma.rn.f32x2 %0, %1, %2, %0;" : "+l"(d) : "l"(a), "l"(b))

__device__ __forceinline__ unsigned long long dup2(float v) {
    unsigned long long d;
    unsigned u = __float_as_uint(v);
    asm("mov.b64 %0, {%1, %1};" : "=l"(d) : "r"(u));
    return d;
}
__device__ __forceinline__ unsigned long long pack2(float2 v) {
    unsigned long long d;
    asm("mov.b64 %0, {%1, %2};" : "=l"(d) : "r"(__float_as_uint(v.x)), "r"(__float_as_uint(v.y)));
    return d;
}
__device__ __forceinline__ float lo32(unsigned long long v) { return __uint_as_float((unsigned)v); }
__device__ __forceinline__ float hi32(unsigned long long v) { return __uint_as_float((unsigned)(v >> 32)); }

__device__ __forceinline__ uint32_t smem_u32(const void* p) {
    uint32_t a;
    asm("{ .reg .u64 t; cvta.to.shared.u64 t, %1; cvt.u32.u64 %0, t; }" : "=r"(a) : "l"(p));
    return a;
}

// bf16 hi/lo split of a float pair -> two packed bf16x2
__device__ __forceinline__ void bf16_split2(float x, float y, uint32_t& hi, uint32_t& lo) {
    const __nv_bfloat162 h = __floats2bfloat162_rn(x, y);
    hi = *(const uint32_t*)&h;
    const float rx = x - __bfloat162float(__low2bfloat16(h));
    const float ry = y - __bfloat162float(__high2bfloat16(h));
    const __nv_bfloat162 l = __floats2bfloat162_rn(rx, ry);
    lo = *(const uint32_t*)&l;
}

// mma.sync m16n8k16 row.col f32 += bf16 * bf16
#define MMA_BF16(d, a, b0, b1)                                                   \
    asm volatile("mma.sync.aligned.m16n8k16.row.col.f32.bf16.bf16.f32 "          \
        "{%0,%1,%2,%3}, {%4,%5,%6,%7}, {%8,%9}, {%0,%1,%2,%3};"                  \
        : "+f"((d)[0]), "+f"((d)[1]), "+f"((d)[2]), "+f"((d)[3])                 \
        : "r"((a)[0]), "r"((a)[1]), "r"((a)[2]), "r"((a)[3]),                    \
          "r"(b0), "r"(b1))

#define LDMATRIX_X4(r, addr)                                                     \
    asm volatile("ldmatrix.sync.aligned.m8n8.x4.shared.b16 {%0,%1,%2,%3}, [%4];" \
        : "=r"((r)[0]), "=r"((r)[1]), "=r"((r)[2]), "=r"((r)[3]) : "r"(addr))

// ---------------- Kernel A0: convert H -> fp16 ----------------
__global__ void convert_kernel(const float* __restrict__ H) {
    const int i = blockIdx.x * blockDim.x + threadIdx.x;
    if (i >= N_NODES * DIM / 4) return;
    const float4 v = ((const float4*)H)[i];
    const __half2 h0 = __floats2half2_rn(v.x, v.y);
    const __half2 h1 = __floats2half2_rn(v.z, v.w);
    uint2 o;
    o.x = *(const unsigned*)&h0;
    o.y = *(const unsigned*)&h1;
    ((uint2*)g_Hh)[i] = o;
}

// ---------------- Kernel A1: W^T -> bf16 hi/lo  (Wt[n][k] = W[k][n]) ----------------
__global__ void prep_w_kernel(const float* __restrict__ W) {
    const int i = blockIdx.x * blockDim.x + threadIdx.x;
    if (i >= DIM * DIM) return;
    const int n = i >> 7, k = i & 127;
    const float w = W[k * DIM + n];
    const __nv_bfloat16 bh = __float2bfloat16(w);
    const float rem = w - __bfloat162float(bh);
    const __nv_bfloat16 bl = __float2bfloat16(rem);
    g_Wth[n * DIM + k] = *(const unsigned short*)&bh;
    g_Wtl[n * DIM + k] = *(const unsigned short*)&bl;
}

// ---------------- Kernel A2: offsets via coalesced boundary scan ----------------
__global__ void scan_offsets_kernel(const int* __restrict__ dst) {
    __shared__ int sd[257];
    const int i = blockIdx.x * blockDim.x + threadIdx.x;
    const int t = threadIdx.x;
    int d = (i < N_EDGES) ? dst[i] : N_NODES;
    sd[t + 1] = d;
    if (t == 0) sd[0] = (i == 0) ? -1 : dst[i - 1];
    __syncthreads();
    if (i >= N_EDGES) return;
    const int prev = sd[t];
    for (int j = prev + 1; j <= d; j++) g_row_off[j] = i;
    if (i == N_EDGES - 1) {
        for (int j = d + 1; j <= N_NODES; j++) g_row_off[j] = N_EDGES;
    }
}

// ---------------- Kernel B: gather-aggregate, warp-per-node, fp16 H ----------------
__global__ __launch_bounds__(256)
void gather_kernel(const int* __restrict__ esrc,
                   const float* __restrict__ ew)
{
    const int lane = threadIdx.x & 31;
    const int node = blockIdx.x * 8 + (threadIdx.x >> 5);

    const int s = g_row_off[node];
    const int e = g_row_off[node + 1];

    const uint2* __restrict__ Hh2 = (const uint2*)g_Hh;
    unsigned long long acc0 = 0ull, acc1 = 0ull;

    #pragma unroll 1
    for (int p = s; p < e; p += 32) {
        const int idx = p + lane;
        int   src = 0;
        float w   = 0.f;
        if (idx < e) { src = esrc[idx]; w = ew[idx]; }
        const int cnt = min(32, e - p);
        if (cnt == 32) {
            #pragma unroll
            for (int g = 0; g < 32; g += 4) {
                int   ss[4];
                float ws[4];
                #pragma unroll
                for (int i = 0; i < 4; i++) {
                    ss[i] = __shfl_sync(0xffffffffu, src, g + i);
                    ws[i] = __shfl_sync(0xffffffffu, w,   g + i);
                }
                uint2 hv[4];
                #pragma unroll
                for (int i = 0; i < 4; i++)
                    hv[i] = Hh2[(size_t)ss[i] * 32 + lane];
                #pragma unroll
                for (int i = 0; i < 4; i++) {
                    const unsigned long long wd = dup2(ws[i]);
                    const float2 f01 = __half22float2(*(const __half2*)&hv[i].x);
                    const float2 f23 = __half22float2(*(const __half2*)&hv[i].y);
                    FFMA2(acc0, wd, pack2(f01));
                    FFMA2(acc1, wd, pack2(f23));
                }
            }
        } else {
            #pragma unroll 1
            for (int g = 0; g < cnt; g += 4) {
                int   ss[4];
                float ws[4];
                #pragma unroll
                for (int i = 0; i < 4; i++) {
                    ss[i] = __shfl_sync(0xffffffffu, src, g + i);
                    ws[i] = __shfl_sync(0xffffffffu, w,   g + i);
                }
                uint2 hv[4];
                #pragma unroll
                for (int i = 0; i < 4; i++)
                    hv[i] = Hh2[(size_t)ss[i] * 32 + lane];
                #pragma unroll
                for (int i = 0; i < 4; i++) {
                    const unsigned long long wd = dup2(ws[i]);
                    const float2 f01 = __half22float2(*(const __half2*)&hv[i].x);
                    const float2 f23 = __half22float2(*(const __half2*)&hv[i].y);
                    FFMA2(acc0, wd, pack2(f01));
                    FFMA2(acc1, wd, pack2(f23));
                }
            }
        }
    }

    float4 st;
    st.x = lo32(acc0); st.y = hi32(acc0);
    st.z = lo32(acc1); st.w = hi32(acc1);
    ((float4*)g_agg)[(size_t)node * 32 + lane] = st;
}

// ---------------- Kernel C: mma.sync bf16-split GEMM: out = agg @ W + b ----------------
// Block 64 rows x 128 cols, 8 warps as 2(row) x 4(col); warp tile 32x32.
// A hi/lo and W^T hi/lo all staged in padded smem (272 B row stride, conflict-free).
// D = Ah*Bh + Ah*Bl + Al*Bh, fp32 accum. Zero global loads in the mainloop.
#define RSTRIDE 272
#define SA_H 0
#define SA_L 17408                    // 64*272
#define SW_H 34816                    // + 64*272
#define SW_L 69632                    // + 128*272
#define SMEM_TOT 104448               // + 128*272

__global__ __launch_bounds__(256)
void tensor_gemm_kernel(const float* __restrict__ bias, float* __restrict__ out)
{
    extern __shared__ __align__(16) unsigned char dsm[];

    const int tid  = threadIdx.x;
    const int wid  = tid >> 5;
    const int lane = tid & 31;
    const int base = blockIdx.x * 64;
    const int wr   = wid >> 2;        // warp row: 0..1 (32 rows each)
    const int wc   = wid & 3;         // warp col: 0..3 (32 cols each)

    // ---- stage A tile: f32 -> bf16 hi/lo ----
    const float4* __restrict__ A4 = (const float4*)g_agg;
    #pragma unroll
    for (int j = tid; j < 64 * 32; j += 256) {
        const int row = j >> 5;
        const int c4  = j & 31;
        int gr = base + row;
        if (gr >= N_NODES) gr = N_NODES - 1;
        const float4 v = A4[(size_t)gr * 32 + c4];
        uint32_t h01, l01, h23, l23;
        bf16_split2(v.x, v.y, h01, l01);
        bf16_split2(v.z, v.w, h23, l23);
        const uint32_t off = row * RSTRIDE + c4 * 8;
        *(uint32_t*)(dsm + SA_H + off)     = h01;
        *(uint32_t*)(dsm + SA_H + off + 4) = h23;
        *(uint32_t*)(dsm + SA_L + off)     = l01;
        *(uint32_t*)(dsm + SA_L + off + 4) = l23;
    }

    // ---- stage W^T hi/lo (128 n-rows x 256 B) into padded smem ----
    {
        const uint4* __restrict__ WhV = (const uint4*)g_Wth;   // 128 rows x 16 uint4
        const uint4* __restrict__ WlV = (const uint4*)g_Wtl;
        #pragma unroll
        for (int i = tid; i < 128 * 16; i += 256) {
            const int row = i >> 4;
            const int c   = i & 15;
            const uint32_t off = row * RSTRIDE + c * 16;
            *(uint4*)(dsm + SW_H + off) = WhV[i];
            *(uint4*)(dsm + SW_L + off) = WlV[i];
        }
    }
    __syncthreads();

    const uint32_t sb = smem_u32(dsm);

    // ldmatrix lane patterns (verified in R15):
    // A x4: lanes 0-15 -> rows 0-15 (k-low 16B), lanes 16-31 -> same rows, +16 B
    const int aRow   = lane & 15;
    const int aKoff  = (lane & 16) ? 16 : 0;
    // B x4 (non-trans on n-major Wt): lanes 0-7 nt_even rows k-low, 8-15 nt_even k-high,
    //                                 16-23 nt_odd k-low, 24-31 nt_odd k-high
    const int bRow   = (lane & 7) + ((lane & 16) ? 8 : 0);
    const int bKoff  = (lane & 8) ? 16 : 0;

    float acc[2][4][4];               // [rt][nt][frag]
    #pragma unroll
    for (int rt = 0; rt < 2; rt++)
        #pragma unroll
        for (int nt = 0; nt < 4; nt++)
            #pragma unroll
            for (int i = 0; i < 4; i++) acc[rt][nt][i] = 0.f;

    #pragma unroll
    for (int ks = 0; ks < 8; ks++) {
        uint32_t ah[2][4], al[2][4];
        #pragma unroll
        for (int rt = 0; rt < 2; rt++) {
            const uint32_t aoff = (uint32_t)(wr * 32 + rt * 16 + aRow) * RSTRIDE + ks * 32 + aKoff;
            LDMATRIX_X4(ah[rt], sb + SA_H + aoff);
            LDMATRIX_X4(al[rt], sb + SA_L + aoff);
        }
        uint32_t bh[2][4], bl[2][4];   // [pair][frag]; pair covers nt = pair*2, pair*2+1
        #pragma unroll
        for (int pr = 0; pr < 2; pr++) {
            const uint32_t boff = (uint32_t)(wc * 32 + pr * 16 + bRow) * RSTRIDE + ks * 32 + bKoff;
            LDMATRIX_X4(bh[pr], sb + SW_H + boff);
            LDMATRIX_X4(bl[pr], sb + SW_L + boff);
        }
        #pragma unroll
        for (int rt = 0; rt < 2; rt++)
            #pragma unroll
            for (int pr = 0; pr < 2; pr++)
                #pragma unroll
                for (int sub = 0; sub < 2; sub++) {
                    const int nt = pr * 2 + sub;
                    MMA_BF16(acc[rt][nt], ah[rt], bh[pr][sub * 2], bh[pr][sub * 2 + 1]);
                    MMA_BF16(acc[rt][nt], ah[rt], bl[pr][sub * 2], bl[pr][sub * 2 + 1]);
                    MMA_BF16(acc[rt][nt], al[rt], bh[pr][sub * 2], bh[pr][sub * 2 + 1]);
                }
    }

    // ---- epilogue: bias + store ----
    const int g  = lane >> 2;
    const int tg = lane & 3;
    float2 bv[4];
    #pragma unroll
    for (int nt = 0; nt < 4; nt++)
        bv[nt] = *(const float2*)&bias[wc * 32 + nt * 8 + tg * 2];

    #pragma unroll
    for (int rt = 0; rt < 2; rt++) {
        const int r0 = base + wr * 32 + rt * 16 + g;
        const int r1 = r0 + 8;
        #pragma unroll
        for (int nt = 0; nt < 4; nt++) {
            const int col = wc * 32 + nt * 8 + tg * 2;
            if (r0 < N_NODES) {
                float2 o;
                o.x = acc[rt][nt][0] + bv[nt].x;
                o.y = acc[rt][nt][1] + bv[nt].y;
                *(float2*)&out[(size_t)r0 * DIM + col] = o;
            }
            if (r1 < N_NODES) {
                float2 o;
                o.x = acc[rt][nt][2] + bv[nt].x;
                o.y = acc[rt][nt][3] + bv[nt].y;
                *(float2*)&out[(size_t)r1 * DIM + col] = o;
            }
        }
    }
}

extern "C" void kernel_launch(void* const* d_in, const int* in_sizes, int n_in,
                              void* d_out, int out_size) {
    const float* H    = (const float*)d_in[0];
    const int*   esrc = (const int*)  d_in[1];
    const int*   edst = (const int*)  d_in[2];
    const float* ew   = (const float*)d_in[3];
    const float* W    = (const float*)d_in[4];
    const float* b    = (const float*)d_in[5];
    float* out = (float*)d_out;

    // host-side attribute set (idempotent, not a stream op; capture-safe)
    cudaFuncSetAttribute(tensor_gemm_kernel,
                         cudaFuncAttributeMaxDynamicSharedMemorySize, SMEM_TOT);

    convert_kernel<<<(N_NODES * DIM / 4 + 255) / 256, 256>>>(H);
    prep_w_kernel<<<(DIM * DIM + 255) / 256, 256>>>(W);
    scan_offsets_kernel<<<(N_EDGES + 255) / 256, 256>>>(edst);
    gather_kernel<<<N_NODES / 8, 256>>>(esrc, ew);
    tensor_gemm_kernel<<<(N_NODES + 63) / 64, 256, SMEM_TOT>>>(b, out);
}